// round 2
// baseline (speedup 1.0000x reference)
#include <cuda_runtime.h>

// Problem constants (fixed by the reference).
#define B_ROWS 16
#define D_LEN  2097152           // floats per row
#define D4_LEN (D_LEN / 4)       // float4 per row = 524288
#define BLOCKS_PER_ROW 64
#define CHUNK4 (D4_LEN / BLOCKS_PER_ROW)   // 8192 float4 per block
#define THREADS 256

// Deterministic scratch: per-(row, block) partial sum of squared diffs.
__device__ float g_partial[B_ROWS * BLOCKS_PER_ROW];

__global__ __launch_bounds__(THREADS)
void sqdiff_partial_kernel(const float4* __restrict__ out,
                           const float4* __restrict__ lab) {
    const int row = blockIdx.y;
    const int blk = blockIdx.x;
    const size_t base = (size_t)row * D4_LEN + (size_t)blk * CHUNK4;

    float acc = 0.0f;
    // 32 iterations per thread; unroll 4 to batch 8 independent 16B loads
    // in flight per thread (high MLP hides DRAM latency).
    #pragma unroll 4
    for (int i = threadIdx.x; i < CHUNK4; i += THREADS) {
        float4 a = __ldg(&out[base + i]);
        float4 b = __ldg(&lab[base + i]);
        float dx = a.x - b.x;
        float dy = a.y - b.y;
        float dz = a.z - b.z;
        float dw = a.w - b.w;
        acc = fmaf(dx, dx, acc);
        acc = fmaf(dy, dy, acc);
        acc = fmaf(dz, dz, acc);
        acc = fmaf(dw, dw, acc);
    }

    // Block reduction: warp shuffle, then shared across 8 warps.
    __shared__ float s_warp[THREADS / 32];
    #pragma unroll
    for (int off = 16; off > 0; off >>= 1)
        acc += __shfl_xor_sync(0xFFFFFFFFu, acc, off);
    const int lane = threadIdx.x & 31;
    const int wid  = threadIdx.x >> 5;
    if (lane == 0) s_warp[wid] = acc;
    __syncthreads();
    if (wid == 0) {
        float v = (lane < THREADS / 32) ? s_warp[lane] : 0.0f;
        #pragma unroll
        for (int off = 4; off > 0; off >>= 1)
            v += __shfl_xor_sync(0xFFFFFFFFu, v, off);
        if (lane == 0)
            g_partial[row * BLOCKS_PER_ROW + blk] = v;
    }
}

// Finalize: one block, 512 threads = 16 warps. Warp w reduces row w's 64
// partials, takes sqrt, then thread 0 averages the 16 distances.
__global__ __launch_bounds__(512)
void finalize_kernel(float* __restrict__ result) {
    const int wid  = threadIdx.x >> 5;   // row index, 0..15
    const int lane = threadIdx.x & 31;

    float v = g_partial[wid * BLOCKS_PER_ROW + lane]
            + g_partial[wid * BLOCKS_PER_ROW + 32 + lane];
    #pragma unroll
    for (int off = 16; off > 0; off >>= 1)
        v += __shfl_xor_sync(0xFFFFFFFFu, v, off);

    __shared__ float s_dist[B_ROWS];
    if (lane == 0) s_dist[wid] = sqrtf(v);
    __syncthreads();

    if (threadIdx.x == 0) {
        float sum = 0.0f;
        #pragma unroll
        for (int r = 0; r < B_ROWS; r++) sum += s_dist[r];
        result[0] = sum / (float)B_ROWS;
    }
}

extern "C" void kernel_launch(void* const* d_in, const int* in_sizes, int n_in,
                              void* d_out, int out_size) {
    const float4* out = (const float4*)d_in[0];
    const float4* lab = (const float4*)d_in[1];
    float* res = (float*)d_out;

    dim3 grid(BLOCKS_PER_ROW, B_ROWS);
    sqdiff_partial_kernel<<<grid, THREADS>>>(out, lab);
    finalize_kernel<<<1, 512>>>(res);
}